// round 16
// baseline (speedup 1.0000x reference)
#include <cuda_runtime.h>

#define NPIL   40000
#define NMAX   32
#define BATCH  4
#define XL     432
#define YL     496
#define OC     64
#define YX     (YL*XL)                 // 214,272
#define OUT_ELEMS (BATCH*OC*YX)        // 54,853,632
#define MAP_ELEMS (BATCH*YX)           // 857,088
#define GPB    8                       // pillar groups per encode block (R12-proven)
#define NBANK  64                      // BN-stat accumulator banks

// Scratch (allocation-free: __device__ globals)
// g_mm layout: [p][cq(16)][ mx0..mx3, mn0..mn3 ]  -> 32B per (p, channel-quad)
__device__ float g_mm [NPIL*OC*2];
__device__ int   g_map[MAP_ELEMS];
__device__ float g_psum [NBANK*OC];    // banked partial sums
__device__ float g_psumq[NBANK*OC];    // banked partial sum-of-squares
__device__ float g_a[OC];
__device__ float g_b[OC];

typedef unsigned long long u64;
__device__ __forceinline__ u64 pk2(float lo, float hi) {
    u64 r; asm("mov.b64 %0, {%1,%2};" : "=l"(r) : "f"(lo), "f"(hi)); return r;
}
__device__ __forceinline__ void upk2(float& lo, float& hi, u64 v) {
    asm("mov.b64 {%0,%1}, %2;" : "=f"(lo), "=f"(hi) : "l"(v));
}
#define FMA2(d,a,b,c) asm("fma.rn.f32x2 %0, %1, %2, %3;" : "=l"(d) : "l"(a), "l"(b), "l"(c))
#define ADD2(d,a,b)   asm("add.rn.f32x2 %0, %1, %2;"     : "=l"(d) : "l"(a), "l"(b))

// ---------------------------------------------------------------------------
// K0: init cell->pillar map to -1; zero banked BN stat accumulators.
// ---------------------------------------------------------------------------
__global__ __launch_bounds__(256) void k_init() {
    unsigned i = blockIdx.x * 256u + threadIdx.x;
    if (i < MAP_ELEMS / 4u)
        ((int4*)g_map)[i] = make_int4(-1, -1, -1, -1);
    if (i < NBANK * OC) {                 // 4096 partials per array
        g_psum[i]  = 0.f;
        g_psumq[i] = 0.f;
    }
}

// ---------------------------------------------------------------------------
// K1: per-pillar encode (R12-proven: 512 threads = 8 pillar-groups x 64
// channels). Stat atomics go to bank (blockIdx & 63) -> 64x less per-address
// serialization at the L2 atomic ALUs.
// ---------------------------------------------------------------------------
__global__ __launch_bounds__(512) void k_encode(const float*  __restrict__ pillars,
                                                const int*    __restrict__ coors,
                                                const int*    __restrict__ npoints,
                                                const float*  __restrict__ W) {
    __shared__ __align__(16) float pts[GPB][4][NMAX];   // [group][comp][n], 4 KB
    __shared__ float wsh[OC * 9];                       // 2.25 KB
    __shared__ float reds[GPB*64], redq[GPB*64];        // 4 KB

    const int tid  = threadIdx.x;
    const int g    = tid >> 6;            // pillar-group in block (0..7)
    const int o    = tid & 63;            // output channel
    const int lane = tid & 31;

    for (int i = tid; i < OC * 9; i += GPB*64) wsh[i] = W[i];

    const int p = blockIdx.x * GPB + g;
    {
        const float2* src = (const float2*)(pillars + (size_t)p * NMAX * 4);
        float2 f = src[o];
        int e0 = 2 * o;
        pts[g][e0 & 3][e0 >> 2]       = f.x;
        pts[g][(e0 + 1) & 3][e0 >> 2] = f.y;
    }
    __syncthreads();

    const float w4 = wsh[o*9+4], w5 = wsh[o*9+5], w6 = wsh[o*9+6],
                w7 = wsh[o*9+7], w8 = wsh[o*9+8];
    const float A0 = wsh[o*9+0] + w4 + w7;
    const float A1 = wsh[o*9+1] + w5 + w8;
    const float A2 = wsh[o*9+2] + w6;
    const float A3 = wsh[o*9+3];

    const int npts = npoints[p];
    const int bi   = coors[p*3+0];
    const int cxi  = coors[p*3+1];
    const int cyi  = coors[p*3+2];

    if (o == 0)
        g_map[bi * YX + cyi * XL + cxi] = p;

    // center: sum of ALL 32 points (matches reference); lane l holds point l
    float sx = pts[g][0][lane], sy = pts[g][1][lane], sz = pts[g][2][lane];
    #pragma unroll
    for (int off = 16; off; off >>= 1) {
        sx += __shfl_xor_sync(0xffffffffu, sx, off);
        sy += __shfl_xor_sync(0xffffffffu, sy, off);
        sz += __shfl_xor_sync(0xffffffffu, sz, off);
    }
    const float inv = 1.0f / (float)npts;
    const float mx_ = sx * inv, my_ = sy * inv, mz_ = sz * inv;
    const float cvx = (float)cxi * 0.16f + 0.08f;
    const float cvy = (float)cyi * 0.16f + (-39.6f);
    const float c   = -(w4*mx_ + w5*my_ + w6*mz_ + w7*cvx + w8*cvy);

    const u64 A0p = pk2(A0, A0), A1p = pk2(A1, A1),
              A2p = pk2(A2, A2), A3p = pk2(A3, A3), cp = pk2(c, c);

    float xmx = -3.4e38f, xmn = 3.4e38f;
    u64 ssum2 = 0ull, ssq2 = 0ull;
    const int npair = npts & ~1;
    for (int n = 0; n < npair; n += 2) {
        u64 qx = *(const u64*)&pts[g][0][n];
        u64 qy = *(const u64*)&pts[g][1][n];
        u64 qz = *(const u64*)&pts[g][2][n];
        u64 qw = *(const u64*)&pts[g][3][n];
        u64 x = cp;
        FMA2(x, A0p, qx, x);
        FMA2(x, A1p, qy, x);
        FMA2(x, A2p, qz, x);
        FMA2(x, A3p, qw, x);
        ADD2(ssum2, ssum2, x);
        FMA2(ssq2, x, x, ssq2);
        float x0, x1; upk2(x0, x1, x);
        xmx = fmaxf(xmx, fmaxf(x0, x1));
        xmn = fminf(xmn, fminf(x0, x1));
    }
    float ssum, ssq;
    { float a0, a1, b0, b1; upk2(a0, a1, ssum2); upk2(b0, b1, ssq2);
      ssum = a0 + a1; ssq = b0 + b1; }
    if (npts & 1) {                        // odd tail
        int n = npair;
        float x = c;
        x = fmaf(A0, pts[g][0][n], x);
        x = fmaf(A1, pts[g][1][n], x);
        x = fmaf(A2, pts[g][2][n], x);
        x = fmaf(A3, pts[g][3][n], x);
        ssum += x; ssq = fmaf(x, x, ssq);
        xmx = fmaxf(xmx, x); xmn = fminf(xmn, x);
    }
    if (npts < NMAX) { xmx = fmaxf(xmx, 0.f); xmn = fminf(xmn, 0.f); }

    const size_t mmb = (size_t)p * (OC*2) + (size_t)(o >> 2) * 8 + (o & 3);
    g_mm[mmb]     = xmx;
    g_mm[mmb + 4] = xmn;

    reds[tid] = ssum; redq[tid] = ssq;
    __syncthreads();
    if (tid < OC) {
        float ts = 0.f, tq = 0.f;
        #pragma unroll
        for (int k = 0; k < GPB; k++) {
            ts += reds[k*64 + tid];
            tq += redq[k*64 + tid];
        }
        const int bank = blockIdx.x & (NBANK - 1);
        atomicAdd(&g_psum [bank * OC + tid], ts);
        atomicAdd(&g_psumq[bank * OC + tid], tq);
    }
}

// ---------------------------------------------------------------------------
// K2: finalize BN affine coefficients. 512 threads = 8 chunks x 64 channels
// reduce the 64 banks, then thread < 64 computes a,b.
// ---------------------------------------------------------------------------
__global__ __launch_bounds__(512) void k_bn(const float* __restrict__ gamma,
                                            const float* __restrict__ beta) {
    __shared__ float rs[512], rq[512];
    const int tid = threadIdx.x;
    const int o   = tid & 63;
    const int ck  = tid >> 6;             // 0..7
    float s = 0.f, q = 0.f;
    #pragma unroll
    for (int k = ck; k < NBANK; k += 8) {
        s += g_psum [k * OC + o];
        q += g_psumq[k * OC + o];
    }
    rs[tid] = s; rq[tid] = q;
    __syncthreads();
    if (tid < OC) {
        float ts = 0.f, tq = 0.f;
        #pragma unroll
        for (int k = 0; k < 8; k++) { ts += rs[k*64 + tid]; tq += rq[k*64 + tid]; }
        const float cnt  = (float)NPIL * (float)NMAX;
        const float mean = ts / cnt;
        const float var  = tq / cnt - mean * mean;
        const float a    = gamma[tid] * rsqrtf(var + 1e-3f);
        g_a[tid] = a;
        g_b[tid] = beta[tid] - mean * a;
    }
}

// ---------------------------------------------------------------------------
// K3: coalesced gather-fill (R11-proven, FROZEN).
// blockDim=(108,2), grid=(YL, 16, BATCH): y is the fastest block dim so
// concurrent CTAs sweep y linearly within a narrow band of planes (dense
// DRAM write window). Thread = 4 x-cells x 2 channels; two coalesced
// float4 streaming stores.
// max_n relu(a*x+b) = relu(a*xmax+b) if a>=0 else relu(a*xmin+b)
// ---------------------------------------------------------------------------
__global__ __launch_bounds__(216) void k_fill(float* __restrict__ out) {
    const unsigned xq = threadIdx.x;                    // 0..107
    const unsigned cp = blockIdx.y * 2u + threadIdx.y;  // 0..31
    const unsigned y  = blockIdx.x;                     // 0..495
    const unsigned b  = blockIdx.z;

    const int4 m = *(const int4*)&g_map[(b * YL + y) * XL + xq * 4];

    const float2 a  = *(const float2*)&g_a[cp * 2];
    const float2 bb = *(const float2*)&g_b[cp * 2];

    // mm offset for this channel-pair inside a pillar's 128-float record:
    // quad cq = cp>>1, within-quad lane = (cp&1)*2 ; mx at +0, mn at +4
    const unsigned mmoff = (cp >> 1) * 8u + (cp & 1) * 2u;

    float2 vv0, vv1, vv2, vv3;
    {
        const float2 z = make_float2(0.f, 0.f);
        vv0 = z; vv1 = z; vv2 = z; vv3 = z;
        if (m.x >= 0) {
            const float* mm = &g_mm[(size_t)m.x * (OC*2) + mmoff];
            float2 mx = *(const float2*)mm, mn = *(const float2*)(mm + 4);
            vv0.x = fmaxf(fmaf(a.x, (a.x >= 0.f ? mx.x : mn.x), bb.x), 0.f);
            vv0.y = fmaxf(fmaf(a.y, (a.y >= 0.f ? mx.y : mn.y), bb.y), 0.f);
        }
        if (m.y >= 0) {
            const float* mm = &g_mm[(size_t)m.y * (OC*2) + mmoff];
            float2 mx = *(const float2*)mm, mn = *(const float2*)(mm + 4);
            vv1.x = fmaxf(fmaf(a.x, (a.x >= 0.f ? mx.x : mn.x), bb.x), 0.f);
            vv1.y = fmaxf(fmaf(a.y, (a.y >= 0.f ? mx.y : mn.y), bb.y), 0.f);
        }
        if (m.z >= 0) {
            const float* mm = &g_mm[(size_t)m.z * (OC*2) + mmoff];
            float2 mx = *(const float2*)mm, mn = *(const float2*)(mm + 4);
            vv2.x = fmaxf(fmaf(a.x, (a.x >= 0.f ? mx.x : mn.x), bb.x), 0.f);
            vv2.y = fmaxf(fmaf(a.y, (a.y >= 0.f ? mx.y : mn.y), bb.y), 0.f);
        }
        if (m.w >= 0) {
            const float* mm = &g_mm[(size_t)m.w * (OC*2) + mmoff];
            float2 mx = *(const float2*)mm, mn = *(const float2*)(mm + 4);
            vv3.x = fmaxf(fmaf(a.x, (a.x >= 0.f ? mx.x : mn.x), bb.x), 0.f);
            vv3.y = fmaxf(fmaf(a.y, (a.y >= 0.f ? mx.y : mn.y), bb.y), 0.f);
        }
    }

    // 2x4 register transpose: plane j gets component j of each cell
    float4 w0 = make_float4(vv0.x, vv1.x, vv2.x, vv3.x);
    float4 w1 = make_float4(vv0.y, vv1.y, vv2.y, vv3.y);

    size_t base = (((size_t)b * OC + cp*2) * YL + y) * XL + xq * 4;
    __stcs((float4*)(out + base),              w0);
    __stcs((float4*)(out + base + (size_t)YX), w1);
}

// ---------------------------------------------------------------------------
extern "C" void kernel_launch(void* const* d_in, const int* in_sizes, int n_in,
                              void* d_out, int out_size) {
    const float* pillars = (const float*)d_in[0];
    const int*   coors   = (const int*)  d_in[1];
    const int*   npoints = (const int*)  d_in[2];
    const float* W       = (const float*)d_in[3];
    const float* gamma   = (const float*)d_in[4];
    const float* beta    = (const float*)d_in[5];
    float* out = (float*)d_out;

    k_init  <<<(MAP_ELEMS/4 + 255) / 256, 256>>>();
    k_encode<<<NPIL / GPB, 512>>>(pillars, coors, npoints, W);
    k_bn    <<<1, 512>>>(gamma, beta);
    dim3 fb(108, 2, 1);
    dim3 fg(YL, 16, BATCH);
    k_fill  <<<fg, fb>>>(out);
}

// round 17
// speedup vs baseline: 1.5392x; 1.5392x over previous
#include <cuda_runtime.h>

#define NPIL   40000
#define NMAX   32
#define BATCH  4
#define XL     432
#define YL     496
#define OC     64
#define YX     (YL*XL)                 // 214,272
#define OUT_ELEMS (BATCH*OC*YX)        // 54,853,632
#define MAP_ELEMS (BATCH*YX)           // 857,088
#define GPB    8                       // pillar groups per encode block (R12-proven)

// Scratch (allocation-free: __device__ globals)
// g_mm layout: [p][cp(32)][ mx_even, mx_odd, mn_even, mn_odd ]
//   -> one 16B record per (pillar, channel-pair); single LDG.128 in fill.
__device__ float g_mm [NPIL*OC*2];
__device__ int   g_map[MAP_ELEMS];
__device__ float g_sum[OC];
__device__ float g_sumsq[OC];
__device__ float g_a[OC];
__device__ float g_b[OC];

typedef unsigned long long u64;
__device__ __forceinline__ u64 pk2(float lo, float hi) {
    u64 r; asm("mov.b64 %0, {%1,%2};" : "=l"(r) : "f"(lo), "f"(hi)); return r;
}
__device__ __forceinline__ void upk2(float& lo, float& hi, u64 v) {
    asm("mov.b64 {%0,%1}, %2;" : "=f"(lo), "=f"(hi) : "l"(v));
}
#define FMA2(d,a,b,c) asm("fma.rn.f32x2 %0, %1, %2, %3;" : "=l"(d) : "l"(a), "l"(b), "l"(c))
#define ADD2(d,a,b)   asm("add.rn.f32x2 %0, %1, %2;"     : "=l"(d) : "l"(a), "l"(b))

// ---------------------------------------------------------------------------
// K0: init cell->pillar map to -1; zero BN stat accumulators. (R12-proven)
// ---------------------------------------------------------------------------
__global__ __launch_bounds__(256) void k_init() {
    unsigned i = blockIdx.x * 256u + threadIdx.x;
    if (i < MAP_ELEMS / 4u)
        ((int4*)g_map)[i] = make_int4(-1, -1, -1, -1);
    if (blockIdx.x == 0 && threadIdx.x < OC) {
        g_sum[threadIdx.x]   = 0.f;
        g_sumsq[threadIdx.x] = 0.f;
    }
}

// ---------------------------------------------------------------------------
// K1: per-pillar encode (R12-proven: 512 threads = 8 pillar-groups x 64
// channels; direct atomics to g_sum/g_sumsq). Only the g_mm store offsets
// differ from R12 (packed per-pair records).
// ---------------------------------------------------------------------------
__global__ __launch_bounds__(512) void k_encode(const float*  __restrict__ pillars,
                                                const int*    __restrict__ coors,
                                                const int*    __restrict__ npoints,
                                                const float*  __restrict__ W) {
    __shared__ __align__(16) float pts[GPB][4][NMAX];   // [group][comp][n], 4 KB
    __shared__ float wsh[OC * 9];                       // 2.25 KB
    __shared__ float reds[GPB*64], redq[GPB*64];        // 4 KB

    const int tid  = threadIdx.x;
    const int g    = tid >> 6;            // pillar-group in block (0..7)
    const int o    = tid & 63;            // output channel
    const int lane = tid & 31;

    for (int i = tid; i < OC * 9; i += GPB*64) wsh[i] = W[i];

    const int p = blockIdx.x * GPB + g;
    {
        const float2* src = (const float2*)(pillars + (size_t)p * NMAX * 4);
        float2 f = src[o];
        int e0 = 2 * o;
        pts[g][e0 & 3][e0 >> 2]       = f.x;
        pts[g][(e0 + 1) & 3][e0 >> 2] = f.y;
    }
    __syncthreads();

    const float w4 = wsh[o*9+4], w5 = wsh[o*9+5], w6 = wsh[o*9+6],
                w7 = wsh[o*9+7], w8 = wsh[o*9+8];
    const float A0 = wsh[o*9+0] + w4 + w7;
    const float A1 = wsh[o*9+1] + w5 + w8;
    const float A2 = wsh[o*9+2] + w6;
    const float A3 = wsh[o*9+3];

    const int npts = npoints[p];
    const int bi   = coors[p*3+0];
    const int cxi  = coors[p*3+1];
    const int cyi  = coors[p*3+2];

    if (o == 0)
        g_map[bi * YX + cyi * XL + cxi] = p;

    // center: sum of ALL 32 points (matches reference); lane l holds point l
    float sx = pts[g][0][lane], sy = pts[g][1][lane], sz = pts[g][2][lane];
    #pragma unroll
    for (int off = 16; off; off >>= 1) {
        sx += __shfl_xor_sync(0xffffffffu, sx, off);
        sy += __shfl_xor_sync(0xffffffffu, sy, off);
        sz += __shfl_xor_sync(0xffffffffu, sz, off);
    }
    const float inv = 1.0f / (float)npts;
    const float mx_ = sx * inv, my_ = sy * inv, mz_ = sz * inv;
    const float cvx = (float)cxi * 0.16f + 0.08f;
    const float cvy = (float)cyi * 0.16f + (-39.6f);
    const float c   = -(w4*mx_ + w5*my_ + w6*mz_ + w7*cvx + w8*cvy);

    const u64 A0p = pk2(A0, A0), A1p = pk2(A1, A1),
              A2p = pk2(A2, A2), A3p = pk2(A3, A3), cp = pk2(c, c);

    float xmx = -3.4e38f, xmn = 3.4e38f;
    u64 ssum2 = 0ull, ssq2 = 0ull;
    const int npair = npts & ~1;
    for (int n = 0; n < npair; n += 2) {
        u64 qx = *(const u64*)&pts[g][0][n];
        u64 qy = *(const u64*)&pts[g][1][n];
        u64 qz = *(const u64*)&pts[g][2][n];
        u64 qw = *(const u64*)&pts[g][3][n];
        u64 x = cp;
        FMA2(x, A0p, qx, x);
        FMA2(x, A1p, qy, x);
        FMA2(x, A2p, qz, x);
        FMA2(x, A3p, qw, x);
        ADD2(ssum2, ssum2, x);
        FMA2(ssq2, x, x, ssq2);
        float x0, x1; upk2(x0, x1, x);
        xmx = fmaxf(xmx, fmaxf(x0, x1));
        xmn = fminf(xmn, fminf(x0, x1));
    }
    float ssum, ssq;
    { float a0, a1, b0, b1; upk2(a0, a1, ssum2); upk2(b0, b1, ssq2);
      ssum = a0 + a1; ssq = b0 + b1; }
    if (npts & 1) {                        // odd tail
        int n = npair;
        float x = c;
        x = fmaf(A0, pts[g][0][n], x);
        x = fmaf(A1, pts[g][1][n], x);
        x = fmaf(A2, pts[g][2][n], x);
        x = fmaf(A3, pts[g][3][n], x);
        ssum += x; ssq = fmaf(x, x, ssq);
        xmx = fmaxf(xmx, x); xmn = fminf(xmn, x);
    }
    if (npts < NMAX) { xmx = fmaxf(xmx, 0.f); xmn = fminf(xmn, 0.f); }

    // packed per-pair record: [p][o>>1][ (o&1) -> mx, +2 -> mn ]
    const size_t mmb = (size_t)p * (OC*2) + (size_t)(o >> 1) * 4 + (o & 1);
    g_mm[mmb]     = xmx;
    g_mm[mmb + 2] = xmn;

    reds[tid] = ssum; redq[tid] = ssq;
    __syncthreads();
    if (tid < OC) {
        float ts = 0.f, tq = 0.f;
        #pragma unroll
        for (int k = 0; k < GPB; k++) {
            ts += reds[k*64 + tid];
            tq += redq[k*64 + tid];
        }
        atomicAdd(&g_sum[tid],   ts);
        atomicAdd(&g_sumsq[tid], tq);
    }
}

// ---------------------------------------------------------------------------
// K2: finalize BN affine coefficients (1 block, R12-proven)
// ---------------------------------------------------------------------------
__global__ void k_bn(const float* __restrict__ gamma, const float* __restrict__ beta) {
    const int o = threadIdx.x;
    const float cnt  = (float)NPIL * (float)NMAX;
    const float mean = g_sum[o] / cnt;
    const float var  = g_sumsq[o] / cnt - mean * mean;
    const float a    = gamma[o] * rsqrtf(var + 1e-3f);
    g_a[o] = a;
    g_b[o] = beta[o] - mean * a;
}

// ---------------------------------------------------------------------------
// K3: coalesced gather-fill (R11-proven structure; packed-record gather).
// blockDim=(108,2), grid=(YL, 16, BATCH); y fastest -> dense DRAM write
// window. Thread = 4 x-cells x 2 channels. ONE LDG.128 per occupied cell
// (was two LDG.64). Two coalesced float4 streaming stores.
// max_n relu(a*x+b) = relu(a*xmax+b) if a>=0 else relu(a*xmin+b)
// ---------------------------------------------------------------------------
__global__ __launch_bounds__(216) void k_fill(float* __restrict__ out) {
    const unsigned xq = threadIdx.x;                    // 0..107
    const unsigned cp = blockIdx.y * 2u + threadIdx.y;  // 0..31
    const unsigned y  = blockIdx.x;                     // 0..495
    const unsigned b  = blockIdx.z;

    const int4 m = *(const int4*)&g_map[(b * YL + y) * XL + xq * 4];

    const float2 a  = *(const float2*)&g_a[cp * 2];
    const float2 bb = *(const float2*)&g_b[cp * 2];

    const unsigned mmoff = cp * 4u;      // packed 16B record offset

    float2 vv0, vv1, vv2, vv3;
    {
        const float2 z = make_float2(0.f, 0.f);
        vv0 = z; vv1 = z; vv2 = z; vv3 = z;
        if (m.x >= 0) {
            float4 q = *(const float4*)&g_mm[(size_t)m.x * (OC*2) + mmoff];
            vv0.x = fmaxf(fmaf(a.x, (a.x >= 0.f ? q.x : q.z), bb.x), 0.f);
            vv0.y = fmaxf(fmaf(a.y, (a.y >= 0.f ? q.y : q.w), bb.y), 0.f);
        }
        if (m.y >= 0) {
            float4 q = *(const float4*)&g_mm[(size_t)m.y * (OC*2) + mmoff];
            vv1.x = fmaxf(fmaf(a.x, (a.x >= 0.f ? q.x : q.z), bb.x), 0.f);
            vv1.y = fmaxf(fmaf(a.y, (a.y >= 0.f ? q.y : q.w), bb.y), 0.f);
        }
        if (m.z >= 0) {
            float4 q = *(const float4*)&g_mm[(size_t)m.z * (OC*2) + mmoff];
            vv2.x = fmaxf(fmaf(a.x, (a.x >= 0.f ? q.x : q.z), bb.x), 0.f);
            vv2.y = fmaxf(fmaf(a.y, (a.y >= 0.f ? q.y : q.w), bb.y), 0.f);
        }
        if (m.w >= 0) {
            float4 q = *(const float4*)&g_mm[(size_t)m.w * (OC*2) + mmoff];
            vv3.x = fmaxf(fmaf(a.x, (a.x >= 0.f ? q.x : q.z), bb.x), 0.f);
            vv3.y = fmaxf(fmaf(a.y, (a.y >= 0.f ? q.y : q.w), bb.y), 0.f);
        }
    }

    // 2x4 register transpose: plane j gets component j of each cell
    float4 w0 = make_float4(vv0.x, vv1.x, vv2.x, vv3.x);
    float4 w1 = make_float4(vv0.y, vv1.y, vv2.y, vv3.y);

    size_t base = (((size_t)b * OC + cp*2) * YL + y) * XL + xq * 4;
    __stcs((float4*)(out + base),              w0);
    __stcs((float4*)(out + base + (size_t)YX), w1);
}

// ---------------------------------------------------------------------------
extern "C" void kernel_launch(void* const* d_in, const int* in_sizes, int n_in,
                              void* d_out, int out_size) {
    const float* pillars = (const float*)d_in[0];
    const int*   coors   = (const int*)  d_in[1];
    const int*   npoints = (const int*)  d_in[2];
    const float* W       = (const float*)d_in[3];
    const float* gamma   = (const float*)d_in[4];
    const float* beta    = (const float*)d_in[5];
    float* out = (float*)d_out;

    k_init  <<<(MAP_ELEMS/4 + 255) / 256, 256>>>();
    k_encode<<<NPIL / GPB, 512>>>(pillars, coors, npoints, W);
    k_bn    <<<1, OC>>>(gamma, beta);
    dim3 fb(108, 2, 1);
    dim3 fg(YL, 16, BATCH);
    k_fill  <<<fg, fb>>>(out);
}